// round 16
// baseline (speedup 1.0000x reference)
#include <cuda_runtime.h>

// LocallyConnected1d: out[b,o,l] = sum_{c,k} x[b,c,l+k]*w[o,c,l,k] + bias[o,l]
// B=32, Cin=128, Cout=128, L=2048, K=3, S=1, W=2050, fp32.
//
// R16 = R15 main kernel (best: pre-transposed x, balanced 16B cp.async
// fills, chunk-swizzled X smem, f32x2 FMA, hoisted x LDS.128) with:
//  - stage loop unroll 2 (compile-time buffer parity)
//  - transpose pre-pass write phase vectorized to STG.128 (was 4x STG.32)

#define CIN     128
#define COUT    128
#define LOUT    2048
#define KW      3
#define WIN     2050

#define L_TILE  32
#define O_TILE  16
#define CC      4                     // Cin per pipeline stage
#define NST     (CIN / CC)            // 32 stages
#define NTHREADS 256

#define STAGE_X (CC * 34 * 32)        // 4352 floats ([ci][w][32b], swizzled)
#define STAGE_W (CC * O_TILE * 96)    // 6144 floats ([ci][oi][96])
#define STAGE_F (STAGE_X + STAGE_W)   // 10496 floats
#define STAGE_BYTES (STAGE_F * 4)     // 41984 B
#define SMEM_BYTES (2 * STAGE_BYTES)  // 83968 B -> 2 blocks/SM

typedef unsigned long long u64;

// x transposed to [c][w][b]: fill reads become 128B-contiguous rows.
__device__ __align__(16) float g_xp[CIN * WIN * 32];

static __device__ __forceinline__ u64 pack_dup(float a) {
    u64 r; asm("mov.b64 %0, {%1, %1};" : "=l"(r) : "f"(a)); return r;
}
static __device__ __forceinline__ void unpack2(u64 v, float& a, float& b) {
    asm("mov.b64 {%0, %1}, %2;" : "=f"(a), "=f"(b) : "l"(v));
}
static __device__ __forceinline__ void ffma2(u64& d, u64 a, u64 b) {
    asm("fma.rn.f32x2 %0, %1, %2, %0;" : "+l"(d) : "l"(a), "l"(b));
}
static __device__ __forceinline__ unsigned smem_u32(const void* p) {
    unsigned r;
    asm("{ .reg .u64 t; cvta.to.shared.u64 t, %1; cvt.u32.u64 %0, t; }"
        : "=r"(r) : "l"(p));
    return r;
}
static __device__ __forceinline__ void cpa16(unsigned d, const float* s) {
    asm volatile("cp.async.cg.shared.global [%0], [%1], 16;" :: "r"(d), "l"(s));
}
static __device__ __forceinline__ void cpa16p(unsigned d, const float* s, bool p) {
    if (p) cpa16(d, s);
}
#define CP_COMMIT() asm volatile("cp.async.commit_group;" ::: "memory")
#define CP_WAIT0()  asm volatile("cp.async.wait_group 0;" ::: "memory")

// ---------------- pre-pass: x[b][c][w] -> g_xp[c][w][b] -------------------
// Read phase: coalesced LDG.32 over w. Write phase: each thread gathers 4
// consecutive-b values from smem (word = (4*b4+i)*33 + w == 4b4+i+w mod 32,
// distinct across the warp for fixed i -> conflict-free) and issues ONE
// STG.128 (b-contiguous, coalesced).
__global__ void __launch_bounds__(256, 4)
transpose_x_kernel(const float* __restrict__ x)
{
    __shared__ float t[32][33];
    const int c  = blockIdx.y;
    const int w0 = blockIdx.x * 32;
    const int tx = threadIdx.x & 31;
    const int ty = threadIdx.x >> 5;

    #pragma unroll
    for (int i = 0; i < 4; i++) {            // read coalesced over w
        int b = ty + i * 8;
        int w = w0 + tx;
        t[b][tx] = (w < WIN) ? x[((long)b * CIN + c) * WIN + w] : 0.f;
    }
    __syncthreads();

    const int w  = threadIdx.x >> 3;         // 0..31
    const int b4 = threadIdx.x & 7;          // float4 index over b
    if (w0 + w < WIN) {
        float4 v = make_float4(t[4*b4+0][w], t[4*b4+1][w],
                               t[4*b4+2][w], t[4*b4+3][w]);
        *reinterpret_cast<float4*>(
            &g_xp[((long)c * WIN + w0 + w) * 32 + 4*b4]) = v;
    }
}

// ------------------------------- main --------------------------------------
__global__ void __launch_bounds__(NTHREADS, 2)
lc1d_kernel(const float* __restrict__ wgt,
            const float* __restrict__ bias,
            float* __restrict__ out)
{
    extern __shared__ float smem[];
    const unsigned sb = smem_u32(smem);

    const int tid  = threadIdx.x;
    const int lane = tid & 31;            // local l index (compute)
    const int warp = tid >> 5;
    const int bp0  = (warp & 3) * 4;      // b-pair group start (compute)
    const int og   = (warp >> 2) * 8;     // o group start (compute)
    const int o0   = blockIdx.x * O_TILE; // o-major raster (x L2 reuse)
    const int l0   = blockIdx.y * L_TILE;

    // ============ fill state: BALANCED across all 8 warps ================
    // X: warp owns ci = warp&3; lower half does ops i=0..3, upper half
    //    i=4..7 + tail. op i: lane -> (w = i*4 + hi, chunk = lo8); dst
    //    chunk swizzled by w&7 (dstE even-i, dstO odd-i).
    // W: warp owns rows (oi = warp*2 + (i>>2), ci = i&3), i=0..7;
    //    lanes 0..23 sweep each 96-float run as float4.
    const int xci  = warp & 3;
    const bool xup = (warp >> 2) != 0;
    const int hi = lane >> 3, lo8 = lane & 7;

    const float* xsrc = g_xp + ((long)(xci * WIN) + l0 + hi) * 32 + lo8 * 4;
    const unsigned dstE = (unsigned)((xci * 34 + hi) * 32 + (lo8 ^ hi) * 4);
    const unsigned dstO = (unsigned)((xci * 34 + hi) * 32 + (lo8 ^ (hi + 4)) * 4);

    const float* wsrc = wgt + ((long)((o0 + warp * 2) * CIN)) * (LOUT * KW)
                            + l0 * KW + lane * 4;
    const unsigned wdst = (unsigned)(STAGE_X + warp * 2 * 96 + lane * 4);

    u64 acc[4][8];
    #pragma unroll
    for (int p = 0; p < 4; p++)
        #pragma unroll
        for (int o = 0; o < 8; o++) acc[p][o] = 0ull;

    #define ISSUE(buf) do {                                                 \
        const unsigned base_ = sb + (unsigned)(buf) * STAGE_BYTES;          \
        unsigned dE_ = base_ + dstE * 4u;                                   \
        unsigned dO_ = base_ + dstO * 4u;                                   \
        if (!xup) {                                                         \
            _Pragma("unroll")                                               \
            for (int i_ = 0; i_ < 4; i_++) {                                \
                unsigned d_ = ((i_ & 1) ? dO_ : dE_) + (unsigned)(i_ * 512);\
                cpa16(d_, xsrc + (long)i_ * 128);                           \
            }                                                               \
        } else {                                                            \
            _Pragma("unroll")                                               \
            for (int i_ = 4; i_ < 8; i_++) {                                \
                unsigned d_ = ((i_ & 1) ? dO_ : dE_) + (unsigned)(i_ * 512);\
                cpa16(d_, xsrc + (long)i_ * 128);                           \
            }                                                               \
            cpa16p(dE_ + 8u * 512u, xsrc + 8L * 128, lane < 16);            \
        }                                                                   \
        xsrc += (long)CC * WIN * 32;                                        \
        if (lane < 24) {                                                    \
            unsigned dW_ = base_ + wdst * 4u;                               \
            _Pragma("unroll")                                               \
            for (int i_ = 0; i_ < 8; i_++)                                  \
                cpa16(dW_ + (unsigned)((((i_ & 3) * 16 + (i_ >> 2)) * 96) * 4), \
                      wsrc + (long)((i_ >> 2) * CIN + (i_ & 3))             \
                           * (LOUT * KW));                                  \
        }                                                                   \
        wsrc += (long)CC * LOUT * KW;                                       \
        CP_COMMIT();                                                        \
    } while (0)

    // prologue: prefetch stage 0
    ISSUE(0);

    const int C0 = bp0 >> 1;              // logical 16B chunk of bp0,bp0+1
    #pragma unroll 2
    for (int s = 0; s < NST; s++) {
        CP_WAIT0();                        // stage s's fills complete
        __syncthreads();                   // visible block-wide; buf s-1 free

        if (s + 1 < NST) {                 // fill s+1; overlaps compute(s)
            ISSUE((s + 1) & 1);
        }

        const float* Xb = smem + (s & 1) * STAGE_F;
        const float* Wb = Xb + STAGE_X;
        const float4* X4 = reinterpret_cast<const float4*>(Xb);

        #pragma unroll
        for (int ci = 0; ci < CC; ci++) {
            // hoist all 6 x LDS.128 for this ci (latency amortized once)
            ulonglong2 va[KW], vb[KW];
            #pragma unroll
            for (int k = 0; k < KW; k++) {
                const int w  = lane + k;
                const int w7 = w & 7;
                const int rb = (ci * 34 + w) * 8;
                va[k] = *reinterpret_cast<const ulonglong2*>(
                            X4 + rb + (C0 ^ w7));
                vb[k] = *reinterpret_cast<const ulonglong2*>(
                            X4 + rb + ((C0 + 1) ^ w7));
            }
            #pragma unroll
            for (int k = 0; k < KW; k++) {
                // w: stride-3 lane addressing, coprime with 32 banks
                const float* wp = Wb + (ci * O_TILE + og) * 96 + lane * KW + k;
                #pragma unroll
                for (int oi = 0; oi < 8; oi++) {
                    u64 wv = pack_dup(wp[oi * 96]);
                    ffma2(acc[0][oi], va[k].x, wv);
                    ffma2(acc[1][oi], va[k].y, wv);
                    ffma2(acc[2][oi], vb[k].x, wv);
                    ffma2(acc[3][oi], vb[k].y, wv);
                }
            }
        }
    }

    // epilogue: bias + coalesced stores (l-contiguous)
    const int b0 = (warp & 3) * 8;
    #pragma unroll
    for (int oi = 0; oi < 8; oi++) {
        int o = o0 + og + oi;
        float bv = bias[o * LOUT + l0 + lane];
        #pragma unroll
        for (int p = 0; p < 4; p++) {
            float f0, f1;
            unpack2(acc[p][oi], f0, f1);
            int b = b0 + 2 * p;
            out[(b * COUT + o) * LOUT + l0 + lane]       = f0 + bv;
            out[((b + 1) * COUT + o) * LOUT + l0 + lane] = f1 + bv;
        }
    }
}

extern "C" void kernel_launch(void* const* d_in, const int* in_sizes, int n_in,
                              void* d_out, int out_size)
{
    const float* x    = (const float*)d_in[0];
    const float* wgt  = (const float*)d_in[1];
    const float* bias = (const float*)d_in[2];
    float* out        = (float*)d_out;

    cudaFuncSetAttribute(lc1d_kernel,
                         cudaFuncAttributeMaxDynamicSharedMemorySize, SMEM_BYTES);

    dim3 tgrid((WIN + 31) / 32, CIN);          // (65, 128)
    transpose_x_kernel<<<tgrid, 256>>>(x);

    dim3 grid(COUT / O_TILE, LOUT / L_TILE);   // (8, 64): o fastest
    lc1d_kernel<<<grid, NTHREADS, SMEM_BYTES>>>(wgt, bias, out);
}